// round 4
// baseline (speedup 1.0000x reference)
#include <cuda_runtime.h>
#include <cstdint>

// Shapes (fixed)
#define BB 32
#define TT 8192
#define II 16
#define HH 128
#define OO 3
#define PP 1024
#define CL 4
#define NTHR 576
#define HXF 160      // floats per hx ring slot: [0..15]=x, [16..143]=h, pad
#define STGF 48      // floats per staging slot (rank0: 16 x + 32 h; others: 32 h)

// Shared layout (float offsets unless noted)
#define OFF_HX 0                  // 3 * 160 = 480
#define OFF_STG 480               // 3 * 48  = 144 -> ends 624
#define OFF_MBAR_BYTES 2496       // bytes 2496..2519 (3 x 8B), = float 624
#define OFF_SUMS 632
#define OFF_CNT  3704
#define SMEM_FLOATS 4728
#define TXB 576                   // per step per CTA: 192 (rank0) + 3*128

typedef unsigned long long u64;

__device__ __forceinline__ uint32_t smem_u32(const void* p) {
    uint32_t a;
    asm("{ .reg .u64 t; cvta.to.shared.u64 t, %1; cvt.u32.u64 %0, t; }"
        : "=r"(a) : "l"(p));
    return a;
}
__device__ __forceinline__ uint32_t mapa_u32(uint32_t a, uint32_t r) {
    uint32_t d;
    asm("mapa.shared::cluster.u32 %0, %1, %2;" : "=r"(d) : "r"(a), "r"(r));
    return d;
}
__device__ __forceinline__ void mbar_init(uint32_t mbar, uint32_t cnt) {
    asm volatile("mbarrier.init.shared.b64 [%0], %1;" :: "r"(mbar), "r"(cnt) : "memory");
}
__device__ __forceinline__ void mbar_expect_tx(uint32_t mbar, uint32_t tx) {
    asm volatile("mbarrier.arrive.expect_tx.shared.b64 _, [%0], %1;"
                 :: "r"(mbar), "r"(tx) : "memory");
}
__device__ __forceinline__ void mbar_wait(uint32_t mbar, unsigned parity) {
    asm volatile(
        "{\n\t.reg .pred P;\n"
        "W%=:\n\t"
        "mbarrier.try_wait.parity.acquire.cta.shared::cta.b64 P, [%0], %1, 10000000;\n\t"
        "@!P bra W%=;\n\t"
        "}" :: "r"(mbar), "r"(parity) : "memory");
}
__device__ __forceinline__ void bulk_s2s(uint32_t dst, uint32_t src, uint32_t bytes,
                                         uint32_t mbar) {
    asm volatile("cp.async.bulk.shared::cluster.shared::cta.mbarrier::complete_tx::bytes "
                 "[%0], [%1], %2, [%3];"
                 :: "r"(dst), "r"(src), "r"(bytes), "r"(mbar) : "memory");
}
__device__ __forceinline__ void fence_async() {
    asm volatile("fence.proxy.async.shared::cta;" ::: "memory");
}
__device__ __forceinline__ u64 pack2(float lo, float hi) {
    u64 p;
    asm("mov.b64 %0, {%1, %2};" : "=l"(p) : "r"(__float_as_uint(lo)), "r"(__float_as_uint(hi)));
    return p;
}
__device__ __forceinline__ void unpack2(float& lo, float& hi, u64 p) {
    uint32_t a, b;
    asm("mov.b64 {%0, %1}, %2;" : "=r"(a), "=r"(b) : "l"(p));
    lo = __uint_as_float(a); hi = __uint_as_float(b);
}
__device__ __forceinline__ u64 ffma2(u64 a, u64 b, u64 c) {
    u64 d;
    asm("fma.rn.f32x2 %0, %1, %2, %3;" : "=l"(d) : "l"(a), "l"(b), "l"(c));
    return d;
}
__device__ __forceinline__ float fsig(float v)  { return __fdividef(1.0f, 1.0f + __expf(-v)); }
__device__ __forceinline__ float ftanh(float v) { return 2.0f * __fdividef(1.0f, 1.0f + __expf(-2.0f * v)) - 1.0f; }

__global__ void __launch_bounds__(NTHR, 1) __cluster_dims__(CL, 1, 1)
lstm_bulk_kernel(const float* __restrict__ x,
                 const float* __restrict__ W_ih,
                 const float* __restrict__ W_hh,
                 const float* __restrict__ b_ih,
                 const float* __restrict__ b_hh,
                 const float* __restrict__ W_fc,
                 const float* __restrict__ b_fc,
                 float* __restrict__ out) {
    __shared__ __align__(16) float smf[SMEM_FLOATS];
    const int tid  = threadIdx.x;
    const int warp = tid >> 5;
    const int lane = tid & 31;
    uint32_t R;
    asm("mov.u32 %0, %%cluster_ctarank;" : "=r"(R));
    const int b = blockIdx.x >> 2;

    const uint32_t sbase = smem_u32(smf);
    uint32_t pbase[CL];
#pragma unroll
    for (int c = 0; c < CL; c++) pbase[c] = mapa_u32(sbase, (uint32_t)c);

    // ---- Prologue ----
    for (int i = tid; i < PP * OO; i += NTHR) smf[OFF_SUMS + i] = 0.0f;
    for (int i = tid; i < PP; i += NTHR)      smf[OFF_CNT + i]  = 0.0f;
    if (tid == 0) {
#pragma unroll
        for (int s = 0; s < 3; s++) mbar_init(sbase + OFF_MBAR_BYTES + 8 * s, 1);
    }
    if (tid < II) smf[OFF_HX + tid]      = x[((size_t)b * TT) * II + tid];  // x(0)
    if (tid < HH) smf[OFF_HX + II + tid] = 0.0f;                            // h(-1)=0
    __syncthreads();
    asm volatile("barrier.cluster.arrive.aligned;" ::: "memory");
    asm volatile("barrier.cluster.wait.aligned;" ::: "memory");

    // ---- Role prologues ----
    // Matvec threads (tid<512): lane = row_in_warp*4 + j; hl = 2*warp + (lane>>4);
    // gate = (lane>>2)&3; row = gate*128 + 32R + hl; k-range [36j, 36j+36) over v=[x|h].
    u64   w2[18];
    float bias = 0.0f, c_state = 0.0f;
    int   j = 0, hl = 0;
    bool  is_h = false;
    if (tid < 512) {
        j = lane & 3;
        const int gate = (lane >> 2) & 3;
        hl = 2 * warp + (lane >> 4);
        const int hg  = 32 * (int)R + hl;
        const int row = gate * HH + hg;
        float4 tmp[9];
        if (j == 0) {
            const float4* wq = (const float4*)(W_ih + (size_t)row * II);
#pragma unroll
            for (int m = 0; m < 4; m++) tmp[m] = wq[m];
            const float4* wp = (const float4*)(W_hh + (size_t)row * HH);
#pragma unroll
            for (int m = 0; m < 5; m++) tmp[4 + m] = wp[m];
            bias = b_ih[row] + b_hh[row];
        } else {
            const float4* wp = (const float4*)(W_hh + (size_t)row * HH + (36 * j - 16));
#pragma unroll
            for (int m = 0; m < 9; m++) tmp[m] = wp[m];
        }
#pragma unroll
        for (int m = 0; m < 9; m++) {
            w2[2 * m]     = pack2(tmp[m].x, tmp[m].y);
            w2[2 * m + 1] = pack2(tmp[m].z, tmp[m].w);
        }
        is_h = ((lane & 15) == 0);   // gate==0 && j==0 -> owns h[hl]
    }
    // FC warp (16)
    float wfc0 = 0.f, wfc1 = 0.f, wfc2 = 0.f, bfc0 = 0.f, bfc1 = 0.f, bfc2 = 0.f;
    if (warp == 16) {
        const int hi = 32 * (int)R + lane;
        wfc0 = W_fc[hi]; wfc1 = W_fc[HH + hi]; wfc2 = W_fc[2 * HH + hi];
        if (R == 0 && lane == 0) { bfc0 = b_fc[0]; bfc1 = b_fc[1]; bfc2 = b_fc[2]; }
    }
    // Comm warp (17): rank 0 prefetches x(t+1)
    float xr = 0.0f;
    if (warp == 17 && R == 0 && lane < II) xr = x[((size_t)b * TT + 1) * II + lane];

    int pid = 0;
    unsigned par0 = 0, par1 = 0, par2 = 0;
    int cur = 0;

    // ---- Time loop ----
    for (int t = 0; t < TT; t++) {
        int nxt = cur + 1; if (nxt == 3) nxt = 0;
        if (t > 0) {
            unsigned parity = (cur == 0) ? par0 : ((cur == 1) ? par1 : par2);
            mbar_wait(sbase + OFF_MBAR_BYTES + 8 * cur, parity);
            if (cur == 0) par0 ^= 1; else if (cur == 1) par1 ^= 1; else par2 ^= 1;
        }
        const float* hxc = smf + OFF_HX + cur * HXF;
        const int stg = OFF_STG + nxt * STGF;

        if (tid < 512) {
            const float4* hp = (const float4*)(hxc + 36 * j);
            u64 aA = pack2(bias, 0.0f);
            u64 aB = pack2(0.0f, 0.0f);
#pragma unroll
            for (int m = 0; m < 9; m++) {
                float4 h4 = hp[m];
                aA = ffma2(w2[2 * m],     pack2(h4.x, h4.y), aA);
                aB = ffma2(w2[2 * m + 1], pack2(h4.z, h4.w), aB);
            }
            float a0, a1, a2, a3;
            unpack2(a0, a1, aA);
            unpack2(a2, a3, aB);
            float pre = (a0 + a1) + (a2 + a3);
            pre += __shfl_xor_sync(0xffffffffu, pre, 1);
            pre += __shfl_xor_sync(0xffffffffu, pre, 2);
            const int gate = (lane >> 2) & 3;
            float act = (gate == 2) ? ftanh(pre) : fsig(pre);
            const int b16 = lane & 16;
            float vi = __shfl_sync(0xffffffffu, act, b16);
            float vf = __shfl_sync(0xffffffffu, act, b16 + 4);
            float vg = __shfl_sync(0xffffffffu, act, b16 + 8);
            float vo = __shfl_sync(0xffffffffu, act, b16 + 12);
            if (is_h) {
                c_state = fmaf(vf, c_state, vi * vg);
                float hval = vo * ftanh(c_state);
                smf[stg + ((R == 0) ? (II + hl) : hl)] = hval;
                fence_async();
            }
        } else if (warp == 16) {
            // FC for h(t-1) (in hxc) against pid captured last step
            const int pid_next = (int)hxc[2];     // x(t)[2]
            if (t > 0) {
                float hv = hxc[II + 32 * (int)R + lane];
                float p0 = hv * wfc0, p1 = hv * wfc1, p2 = hv * wfc2;
#pragma unroll
                for (int o = 16; o > 0; o >>= 1) {
                    p0 += __shfl_down_sync(0xffffffffu, p0, o);
                    p1 += __shfl_down_sync(0xffffffffu, p1, o);
                    p2 += __shfl_down_sync(0xffffffffu, p2, o);
                }
                if (lane == 0 && (unsigned)pid < PP) {
                    float* s = &smf[OFF_SUMS + pid * 3];
                    s[0] += p0 + bfc0; s[1] += p1 + bfc1; s[2] += p2 + bfc2;
                    if (R == 0) smf[OFF_CNT + pid] += 1.0f;
                }
            }
            pid = pid_next;
        } else {
            // Comm warp: rank 0 stages x(t+1) into staging (pre-sync)
            if (R == 0 && lane < II) {
                smf[stg + lane] = xr;
                fence_async();
                xr = (t + 2 < TT) ? x[((size_t)b * TT + t + 2) * II + lane] : 0.0f;
            }
        }
        __syncthreads();
        if (warp == 17) {
            if (lane == 0) {
                const uint32_t src = sbase + (uint32_t)stg * 4u;
                const uint32_t sz  = (R == 0) ? 192u : 128u;
                const uint32_t dof = (uint32_t)(OFF_HX + nxt * HXF) * 4u
                                     + ((R == 0) ? 0u : (64u + 128u * R));
                const uint32_t mbo = (uint32_t)(OFF_MBAR_BYTES + 8 * nxt);
#pragma unroll
                for (int c = 0; c < CL; c++)
                    bulk_s2s(pbase[c] + dof, src, sz, pbase[c] + mbo);
            } else if (lane == 16) {
                mbar_expect_tx(sbase + OFF_MBAR_BYTES + 8 * nxt, TXB);
            }
        }
        cur = nxt;
    }

    // ---- Final FC round for h(TT-1), delivered into buffer 2 ----
    mbar_wait(sbase + OFF_MBAR_BYTES + 8 * 2, par2);
    if (warp == 16) {
        const float* hxc = smf + OFF_HX + 2 * HXF;
        float hv = hxc[II + 32 * (int)R + lane];
        float p0 = hv * wfc0, p1 = hv * wfc1, p2 = hv * wfc2;
#pragma unroll
        for (int o = 16; o > 0; o >>= 1) {
            p0 += __shfl_down_sync(0xffffffffu, p0, o);
            p1 += __shfl_down_sync(0xffffffffu, p1, o);
            p2 += __shfl_down_sync(0xffffffffu, p2, o);
        }
        if (lane == 0 && (unsigned)pid < PP) {
            float* s = &smf[OFF_SUMS + pid * 3];
            s[0] += p0 + bfc0; s[1] += p1 + bfc1; s[2] += p2 + bfc2;
            if (R == 0) smf[OFF_CNT + pid] += 1.0f;
        }
    }
    __syncthreads();
    asm volatile("barrier.cluster.arrive.aligned;" ::: "memory");
    asm volatile("barrier.cluster.wait.aligned;" ::: "memory");

    // ---- Epilogue: rank 0 gathers peer partial sums via DSMEM, writes out ----
    if (R == 0) {
        for (int idx = tid; idx < PP * OO; idx += NTHR) {
            float s = smf[OFF_SUMS + idx];
#pragma unroll
            for (int c = 1; c < CL; c++) {
                const uint32_t ra = pbase[c] + (uint32_t)((OFF_SUMS + idx) * 4);
                float v;
                asm volatile("ld.shared::cluster.f32 %0, [%1];" : "=f"(v) : "r"(ra));
                s += v;
            }
            const int p = idx / 3;
            float cc = smf[OFF_CNT + p];
            if (cc == 0.0f) cc = 1.0f;
            out[(size_t)b * PP * OO + idx] = s / cc;
        }
    }
    asm volatile("barrier.cluster.arrive.aligned;" ::: "memory");
    asm volatile("barrier.cluster.wait.aligned;" ::: "memory");
}

extern "C" void kernel_launch(void* const* d_in, const int* in_sizes, int n_in,
                              void* d_out, int out_size) {
    const float* x    = (const float*)d_in[0];
    const float* W_ih = (const float*)d_in[1];
    const float* W_hh = (const float*)d_in[2];
    const float* b_ih = (const float*)d_in[3];
    const float* b_hh = (const float*)d_in[4];
    const float* W_fc = (const float*)d_in[5];
    const float* b_fc = (const float*)d_in[6];
    float* out = (float*)d_out;
    lstm_bulk_kernel<<<BB * CL, NTHR>>>(x, W_ih, W_hh, b_ih, b_hh, W_fc, b_fc, out);
}

// round 5
// speedup vs baseline: 1.0459x; 1.0459x over previous
#include <cuda_runtime.h>
#include <cstdint>

// Shapes (fixed)
#define BB 32
#define TT 8192
#define II 16
#define HH 128
#define OO 3
#define PP 1024
#define CL 4
#define NTHR 576
#define HXF 160      // floats per hx ring slot: [0..15]=x, [16..143]=h, pad

// Shared layout (float offsets unless noted)
#define OFF_HX 0                  // 3 * 160 = 480
#define OFF_MBAR_BYTES 1920       // bytes 1920..1943 (3 x 8B) = float 480..485
#define OFF_SUMS 488
#define OFF_CNT  3560
#define SMEM_FLOATS 4584

typedef unsigned long long u64;

__device__ __forceinline__ uint32_t smem_u32(const void* p) {
    uint32_t a;
    asm("{ .reg .u64 t; cvta.to.shared.u64 t, %1; cvt.u32.u64 %0, t; }"
        : "=r"(a) : "l"(p));
    return a;
}
__device__ __forceinline__ uint32_t mapa_u32(uint32_t a, uint32_t r) {
    uint32_t d;
    asm("mapa.shared::cluster.u32 %0, %1, %2;" : "=r"(d) : "r"(a), "r"(r));
    return d;
}
__device__ __forceinline__ void mbar_init(uint32_t mbar, uint32_t cnt) {
    asm volatile("mbarrier.init.shared.b64 [%0], %1;" :: "r"(mbar), "r"(cnt) : "memory");
}
__device__ __forceinline__ void mbar_expect_tx(uint32_t mbar, uint32_t tx) {
    asm volatile("mbarrier.arrive.expect_tx.shared.b64 _, [%0], %1;"
                 :: "r"(mbar), "r"(tx) : "memory");
}
__device__ __forceinline__ void mbar_wait(uint32_t mbar, unsigned parity) {
    asm volatile(
        "{\n\t.reg .pred P;\n"
        "W%=:\n\t"
        "mbarrier.try_wait.parity.acquire.cta.shared::cta.b64 P, [%0], %1, 10000000;\n\t"
        "@!P bra W%=;\n\t"
        "}" :: "r"(mbar), "r"(parity) : "memory");
}
__device__ __forceinline__ void st_async_b64(uint32_t addr, u64 v, uint32_t mbar) {
    asm volatile("st.async.shared::cluster.mbarrier::complete_tx::bytes.b64 [%0], %1, [%2];"
                 :: "r"(addr), "l"(v), "r"(mbar) : "memory");
}
__device__ __forceinline__ u64 pack2(float lo, float hi) {
    u64 p;
    asm("mov.b64 %0, {%1, %2};" : "=l"(p) : "r"(__float_as_uint(lo)), "r"(__float_as_uint(hi)));
    return p;
}
__device__ __forceinline__ void unpack2(float& lo, float& hi, u64 p) {
    uint32_t a, b;
    asm("mov.b64 {%0, %1}, %2;" : "=r"(a), "=r"(b) : "l"(p));
    lo = __uint_as_float(a); hi = __uint_as_float(b);
}
__device__ __forceinline__ u64 ffma2(u64 a, u64 b, u64 c) {
    u64 d;
    asm("fma.rn.f32x2 %0, %1, %2, %3;" : "=l"(d) : "l"(a), "l"(b), "l"(c));
    return d;
}
__device__ __forceinline__ float fsig(float v)  { return __fdividef(1.0f, 1.0f + __expf(-v)); }
__device__ __forceinline__ float ftanh(float v) { return 2.0f * __fdividef(1.0f, 1.0f + __expf(-2.0f * v)) - 1.0f; }

__global__ void __launch_bounds__(NTHR, 1) __cluster_dims__(CL, 1, 1)
lstm_pair_kernel(const float* __restrict__ x,
                 const float* __restrict__ W_ih,
                 const float* __restrict__ W_hh,
                 const float* __restrict__ b_ih,
                 const float* __restrict__ b_hh,
                 const float* __restrict__ W_fc,
                 const float* __restrict__ b_fc,
                 float* __restrict__ out) {
    __shared__ __align__(16) float smf[SMEM_FLOATS];
    const int tid  = threadIdx.x;
    const int warp = tid >> 5;
    const int lane = tid & 31;
    uint32_t R;
    asm("mov.u32 %0, %%cluster_ctarank;" : "=r"(R));
    const int b = blockIdx.x >> 2;

    const uint32_t sbase = smem_u32(smf);
    uint32_t pbase[CL];
#pragma unroll
    for (int c = 0; c < CL; c++) pbase[c] = mapa_u32(sbase, (uint32_t)c);
    // Remote peer bases in send order (R+1, R+2, R+3 mod 4)
    uint32_t peer[3];
#pragma unroll
    for (int c = 0; c < 3; c++) peer[c] = pbase[(R + 1 + c) & 3];

    // Expected tx bytes per step at THIS rank's barrier:
    //   h from 3 remote CTAs: 3*32*4 = 384 B; x from rank0 (remote for R!=0): +64 B
    const uint32_t TXB_SELF = (R == 0) ? 384u : 448u;

    // ---- Prologue ----
    for (int i = tid; i < PP * OO; i += NTHR) smf[OFF_SUMS + i] = 0.0f;
    for (int i = tid; i < PP; i += NTHR)      smf[OFF_CNT + i]  = 0.0f;
    if (tid == 0) {
#pragma unroll
        for (int s = 0; s < 3; s++) mbar_init(sbase + OFF_MBAR_BYTES + 8 * s, 1);
    }
    if (tid < II) smf[OFF_HX + tid]      = x[((size_t)b * TT) * II + tid];  // x(0)
    if (tid < HH) smf[OFF_HX + II + tid] = 0.0f;                            // h(-1)=0
    __syncthreads();
    asm volatile("barrier.cluster.arrive.aligned;" ::: "memory");
    asm volatile("barrier.cluster.wait.aligned;" ::: "memory");

    // ---- Role prologues ----
    // Matvec threads (tid<512): lane = row_in_warp*4 + j; hl = 2*warp + (lane>>4);
    // gate = (lane>>2)&3; row = gate*128 + 32R + hl; k-range [36j,36j+36) over v=[x|h].
    u64   w2[18];
    float bias = 0.0f, c_state = 0.0f;
    int   j = 0;
    if (tid < 512) {
        j = lane & 3;
        const int gate = (lane >> 2) & 3;
        const int hl = 2 * warp + (lane >> 4);
        const int hg  = 32 * (int)R + hl;
        const int row = gate * HH + hg;
        float4 tmp[9];
        if (j == 0) {
            const float4* wq = (const float4*)(W_ih + (size_t)row * II);
#pragma unroll
            for (int m = 0; m < 4; m++) tmp[m] = wq[m];
            const float4* wp = (const float4*)(W_hh + (size_t)row * HH);
#pragma unroll
            for (int m = 0; m < 5; m++) tmp[4 + m] = wp[m];
            bias = b_ih[row] + b_hh[row];
        } else {
            const float4* wp = (const float4*)(W_hh + (size_t)row * HH + (36 * j - 16));
#pragma unroll
            for (int m = 0; m < 9; m++) tmp[m] = wp[m];
        }
#pragma unroll
        for (int m = 0; m < 9; m++) {
            w2[2 * m]     = pack2(tmp[m].x, tmp[m].y);
            w2[2 * m + 1] = pack2(tmp[m].z, tmp[m].w);
        }
    }
    // FC warp (16)
    float wfc0 = 0.f, wfc1 = 0.f, wfc2 = 0.f, bfc0 = 0.f, bfc1 = 0.f, bfc2 = 0.f;
    if (warp == 16) {
        const int hi = 32 * (int)R + lane;
        wfc0 = W_fc[hi]; wfc1 = W_fc[HH + hi]; wfc2 = W_fc[2 * HH + hi];
        if (R == 0 && lane == 0) { bfc0 = b_fc[0]; bfc1 = b_fc[1]; bfc2 = b_fc[2]; }
    }
    // Comm warp (17): rank 0, lanes 0..7 hold x(t+1) as float2
    float2 xr = make_float2(0.f, 0.f);
    if (warp == 17 && R == 0 && lane < 8)
        xr = ((const float2*)(x + ((size_t)b * TT + 1) * II))[lane];

    int pid = 0;
    unsigned par0 = 0, par1 = 0, par2 = 0;
    int cur = 0;

    // ---- Time loop ----
    for (int t = 0; t < TT; t++) {
        int nxt = cur + 1; if (nxt == 3) nxt = 0;
        if (t > 0) {
            unsigned parity = (cur == 0) ? par0 : ((cur == 1) ? par1 : par2);
            mbar_wait(sbase + OFF_MBAR_BYTES + 8 * cur, parity);
            if (cur == 0) par0 ^= 1; else if (cur == 1) par1 ^= 1; else par2 ^= 1;
        }
        __syncthreads();   // orders local STS from step t-1 for all readers
        const float* hxc = smf + OFF_HX + cur * HXF;
        const uint32_t nxt_f = (uint32_t)(OFF_HX + nxt * HXF);
        const uint32_t mbo   = (uint32_t)(OFF_MBAR_BYTES + 8 * nxt);

        if (tid < 512) {
            const float4* hp = (const float4*)(hxc + 36 * j);
            u64 aA = pack2(bias, 0.0f);
            u64 aB = pack2(0.0f, 0.0f);
#pragma unroll
            for (int m = 0; m < 9; m++) {
                float4 h4 = hp[m];
                aA = ffma2(w2[2 * m],     pack2(h4.x, h4.y), aA);
                aB = ffma2(w2[2 * m + 1], pack2(h4.z, h4.w), aB);
            }
            float a0, a1, a2, a3;
            unpack2(a0, a1, aA);
            unpack2(a2, a3, aB);
            float pre = (a0 + a1) + (a2 + a3);
            pre += __shfl_xor_sync(0xffffffffu, pre, 1);
            pre += __shfl_xor_sync(0xffffffffu, pre, 2);
            const int gate = (lane >> 2) & 3;
            float act = (gate == 2) ? ftanh(pre) : fsig(pre);
            const int b16 = lane & 16;
            float vi = __shfl_sync(0xffffffffu, act, b16);
            float vf = __shfl_sync(0xffffffffu, act, b16 + 4);
            float vg = __shfl_sync(0xffffffffu, act, b16 + 8);
            float vo = __shfl_sync(0xffffffffu, act, b16 + 12);
            float hval = 0.0f;
            if ((lane & 15) == 0) {           // lanes 0 and 16: own h[2*warp + (lane>>4)]
                c_state = fmaf(vf, c_state, vi * vg);
                hval = vo * ftanh(c_state);
            }
            // pair up: lane0 gets lane16's hval
            float hodd = __shfl_sync(0xffffffffu, hval, 16);
            if (lane == 0) {
                u64 hp2 = pack2(hval, hodd);
                // destination float index: II + 32R + 2*warp within slot nxt
                const uint32_t doff = (nxt_f + II + 32u * R + 2u * (uint32_t)warp) * 4u;
                // remote peers first (latency), then local STS
#pragma unroll
                for (int c = 0; c < 3; c++)
                    st_async_b64(peer[c] + doff, hp2, peer[c] + mbo);
                *(u64*)((char*)smf + doff) = hp2;   // local: plain STS, ordered by next sync
            }
        } else if (warp == 16) {
            // FC for h(t-1) (in hxc) against pid captured last step
            const int pid_next = (int)hxc[2];     // x(t)[2]
            if (t > 0) {
                float hv = hxc[II + 32 * (int)R + lane];
                float p0 = hv * wfc0, p1 = hv * wfc1, p2 = hv * wfc2;
#pragma unroll
                for (int o = 16; o > 0; o >>= 1) {
                    p0 += __shfl_down_sync(0xffffffffu, p0, o);
                    p1 += __shfl_down_sync(0xffffffffu, p1, o);
                    p2 += __shfl_down_sync(0xffffffffu, p2, o);
                }
                if (lane == 0 && (unsigned)pid < PP) {
                    float* s = &smf[OFF_SUMS + pid * 3];
                    s[0] += p0 + bfc0; s[1] += p1 + bfc1; s[2] += p2 + bfc2;
                    if (R == 0) smf[OFF_CNT + pid] += 1.0f;
                }
            }
            pid = pid_next;
        } else {
            // Comm warp: post expect_tx for nxt; rank0 lanes 0..7 deliver x(t+1)
            if (lane == 16) {
                mbar_expect_tx(sbase + mbo, TXB_SELF);
            } else if (R == 0 && lane < 8) {
                u64 xp = pack2(xr.x, xr.y);
                const uint32_t doff = (nxt_f + 2u * (uint32_t)lane) * 4u;
#pragma unroll
                for (int c = 0; c < 3; c++)
                    st_async_b64(peer[c] + doff, xp, peer[c] + mbo);
                *(u64*)((char*)smf + doff) = xp;
                xr = (t + 2 < TT)
                   ? ((const float2*)(x + ((size_t)b * TT + t + 2) * II))[lane]
                   : make_float2(0.f, 0.f);
            }
        }
        cur = nxt;
    }

    // ---- Final FC round for h(TT-1): delivered into buffer 2 (8191%3==1 -> nxt==2) ----
    mbar_wait(sbase + OFF_MBAR_BYTES + 8 * 2, par2);
    __syncthreads();   // order local owners' STS into buffer 2
    if (warp == 16) {
        const float* hxc = smf + OFF_HX + 2 * HXF;
        float hv = hxc[II + 32 * (int)R + lane];
        float p0 = hv * wfc0, p1 = hv * wfc1, p2 = hv * wfc2;
#pragma unroll
        for (int o = 16; o > 0; o >>= 1) {
            p0 += __shfl_down_sync(0xffffffffu, p0, o);
            p1 += __shfl_down_sync(0xffffffffu, p1, o);
            p2 += __shfl_down_sync(0xffffffffu, p2, o);
        }
        if (lane == 0 && (unsigned)pid < PP) {
            float* s = &smf[OFF_SUMS + pid * 3];
            s[0] += p0 + bfc0; s[1] += p1 + bfc1; s[2] += p2 + bfc2;
            if (R == 0) smf[OFF_CNT + pid] += 1.0f;
        }
    }
    __syncthreads();
    asm volatile("barrier.cluster.arrive.aligned;" ::: "memory");
    asm volatile("barrier.cluster.wait.aligned;" ::: "memory");

    // ---- Epilogue: rank 0 gathers peer partial sums via DSMEM, writes out ----
    if (R == 0) {
        for (int idx = tid; idx < PP * OO; idx += NTHR) {
            float s = smf[OFF_SUMS + idx];
#pragma unroll
            for (int c = 1; c < CL; c++) {
                const uint32_t ra = pbase[c] + (uint32_t)((OFF_SUMS + idx) * 4);
                float v;
                asm volatile("ld.shared::cluster.f32 %0, [%1];" : "=f"(v) : "r"(ra));
                s += v;
            }
            const int p = idx / 3;
            float cc = smf[OFF_CNT + p];
            if (cc == 0.0f) cc = 1.0f;
            out[(size_t)b * PP * OO + idx] = s / cc;
        }
    }
    asm volatile("barrier.cluster.arrive.aligned;" ::: "memory");
    asm volatile("barrier.cluster.wait.aligned;" ::: "memory");
}

extern "C" void kernel_launch(void* const* d_in, const int* in_sizes, int n_in,
                              void* d_out, int out_size) {
    const float* x    = (const float*)d_in[0];
    const float* W_ih = (const float*)d_in[1];
    const float* W_hh = (const float*)d_in[2];
    const float* b_ih = (const float*)d_in[3];
    const float* b_hh = (const float*)d_in[4];
    const float* W_fc = (const float*)d_in[5];
    const float* b_fc = (const float*)d_in[6];
    float* out = (float*)d_out;
    lstm_pair_kernel<<<BB * CL, NTHR>>>(x, W_ih, W_hh, b_ih, b_hh, W_fc, b_fc, out);
}

// round 6
// speedup vs baseline: 1.0500x; 1.0039x over previous
#include <cuda_runtime.h>
#include <cstdint>

// Shapes (fixed)
#define BB 32
#define TT 8192
#define II 16
#define HH 128
#define OO 3
#define PP 1024
#define CL 4
#define NTHR 576
#define HXF 160      // floats per hx ring slot: [0..15]=x, [16..143]=h, pad to 160

// Shared layout (float offsets unless noted)
#define OFF_HX 0                  // 3 * 160 = 480
#define OFF_MBAR_BYTES 1920       // bytes 1920..1943 (3 x 8B) = float 480..485
#define OFF_SUMS 488
#define OFF_CNT  3560
#define SMEM_FLOATS 4584
#define TXB 576u                  // per phase per CTA: 64 h-b64 (512B) + 8 x-b64 (64B)

typedef unsigned long long u64;

__device__ __forceinline__ uint32_t smem_u32(const void* p) {
    uint32_t a;
    asm("{ .reg .u64 t; cvta.to.shared.u64 t, %1; cvt.u32.u64 %0, t; }"
        : "=r"(a) : "l"(p));
    return a;
}
__device__ __forceinline__ uint32_t mapa_u32(uint32_t a, uint32_t r) {
    uint32_t d;
    asm("mapa.shared::cluster.u32 %0, %1, %2;" : "=r"(d) : "r"(a), "r"(r));
    return d;
}
__device__ __forceinline__ void mbar_init(uint32_t mbar, uint32_t cnt) {
    asm volatile("mbarrier.init.shared.b64 [%0], %1;" :: "r"(mbar), "r"(cnt) : "memory");
}
__device__ __forceinline__ void mbar_expect_tx(uint32_t mbar, uint32_t tx) {
    asm volatile("mbarrier.arrive.expect_tx.shared.b64 _, [%0], %1;"
                 :: "r"(mbar), "r"(tx) : "memory");
}
__device__ __forceinline__ void mbar_arrive(uint32_t mbar) {
    asm volatile("mbarrier.arrive.release.cta.shared.b64 _, [%0];"
                 :: "r"(mbar) : "memory");
}
__device__ __forceinline__ void mbar_wait(uint32_t mbar, unsigned parity) {
    asm volatile(
        "{\n\t.reg .pred P;\n"
        "W%=:\n\t"
        "mbarrier.try_wait.parity.acquire.cta.shared::cta.b64 P, [%0], %1, 10000000;\n\t"
        "@!P bra W%=;\n\t"
        "}" :: "r"(mbar), "r"(parity) : "memory");
}
__device__ __forceinline__ void st_async_b64(uint32_t addr, u64 v, uint32_t mbar) {
    asm volatile("st.async.shared::cluster.mbarrier::complete_tx::bytes.b64 [%0], %1, [%2];"
                 :: "r"(addr), "l"(v), "r"(mbar) : "memory");
}
__device__ __forceinline__ u64 pack2(float lo, float hi) {
    u64 p;
    asm("mov.b64 %0, {%1, %2};" : "=l"(p) : "r"(__float_as_uint(lo)), "r"(__float_as_uint(hi)));
    return p;
}
__device__ __forceinline__ void unpack2(float& lo, float& hi, u64 p) {
    uint32_t a, b;
    asm("mov.b64 {%0, %1}, %2;" : "=r"(a), "=r"(b) : "l"(p));
    lo = __uint_as_float(a); hi = __uint_as_float(b);
}
__device__ __forceinline__ u64 ffma2(u64 a, u64 b, u64 c) {
    u64 d;
    asm("fma.rn.f32x2 %0, %1, %2, %3;" : "=l"(d) : "l"(a), "l"(b), "l"(c));
    return d;
}
__device__ __forceinline__ float fsig(float v)  { return __fdividef(1.0f, 1.0f + __expf(-v)); }
__device__ __forceinline__ float ftanh(float v) { return 2.0f * __fdividef(1.0f, 1.0f + __expf(-2.0f * v)) - 1.0f; }

__global__ void __launch_bounds__(NTHR, 1) __cluster_dims__(CL, 1, 1)
lstm_nosync_kernel(const float* __restrict__ x,
                   const float* __restrict__ W_ih,
                   const float* __restrict__ W_hh,
                   const float* __restrict__ b_ih,
                   const float* __restrict__ b_hh,
                   const float* __restrict__ W_fc,
                   const float* __restrict__ b_fc,
                   float* __restrict__ out) {
    __shared__ __align__(16) float smf[SMEM_FLOATS];
    const int tid  = threadIdx.x;
    const int warp = tid >> 5;
    const int lane = tid & 31;
    uint32_t R;
    asm("mov.u32 %0, %%cluster_ctarank;" : "=r"(R));
    const int b = blockIdx.x >> 2;

    const uint32_t sbase = smem_u32(smf);
    uint32_t pbase[CL];
#pragma unroll
    for (int c = 0; c < CL; c++) pbase[c] = mapa_u32(sbase, (uint32_t)c);
    uint32_t dst4[CL];   // send order: R+1, R+2, R+3, self
#pragma unroll
    for (int c = 0; c < CL; c++) dst4[c] = pbase[(R + 1 + c) & 3];

    // ---- Prologue ----
    for (int i = tid; i < PP * OO; i += NTHR) smf[OFF_SUMS + i] = 0.0f;
    for (int i = tid; i < PP; i += NTHR)      smf[OFF_CNT + i]  = 0.0f;
    if (tid == 0) {
#pragma unroll
        for (int s = 0; s < 3; s++) mbar_init(sbase + OFF_MBAR_BYTES + 8 * s, 2);
    }
    if (tid < II) smf[OFF_HX + tid]      = x[((size_t)b * TT) * II + tid];  // x(0)
    if (tid < HH) smf[OFF_HX + II + tid] = 0.0f;                            // h(-1)=0
    __syncthreads();
    asm volatile("barrier.cluster.arrive.aligned;" ::: "memory");
    asm volatile("barrier.cluster.wait.aligned;" ::: "memory");

    // ---- Role prologues ----
    // Matvec threads (tid<512): j = lane&3; gate = (lane>>2)&3; hl = 2*warp + (lane>>4);
    // row = gate*128 + 32R + hl; thread covers v[36j .. 36j+36), v = [x(16) | h(128)].
    u64   w2[18];
    u64   biasPack = 0;
    float c_state = 0.0f;
    int   j = 0;
    if (tid < 512) {
        j = lane & 3;
        const int gate = (lane >> 2) & 3;
        const int hl   = 2 * warp + (lane >> 4);
        const int hg   = 32 * (int)R + hl;
        const int row  = gate * HH + hg;
        float4 tmp[9];
        if (j == 0) {
            const float4* wq = (const float4*)(W_ih + (size_t)row * II);
#pragma unroll
            for (int m = 0; m < 4; m++) tmp[m] = wq[m];
            const float4* wp = (const float4*)(W_hh + (size_t)row * HH);
#pragma unroll
            for (int m = 0; m < 5; m++) tmp[4 + m] = wp[m];
            biasPack = pack2(b_ih[row] + b_hh[row], 0.0f);
        } else {
            const float4* wp = (const float4*)(W_hh + (size_t)row * HH + (36 * j - 16));
#pragma unroll
            for (int m = 0; m < 9; m++) tmp[m] = wp[m];
        }
#pragma unroll
        for (int m = 0; m < 9; m++) {
            w2[2 * m]     = pack2(tmp[m].x, tmp[m].y);
            w2[2 * m + 1] = pack2(tmp[m].z, tmp[m].w);
        }
    }
    // FC warp (16)
    float wfc0 = 0.f, wfc1 = 0.f, wfc2 = 0.f, bfc0 = 0.f, bfc1 = 0.f, bfc2 = 0.f;
    if (warp == 16) {
        const int hi = 32 * (int)R + lane;
        wfc0 = W_fc[hi]; wfc1 = W_fc[HH + hi]; wfc2 = W_fc[2 * HH + hi];
        if (R == 0 && lane == 0) { bfc0 = b_fc[0]; bfc1 = b_fc[1]; bfc2 = b_fc[2]; }
    }
    // Comm warp (17): every rank loads its own x. lanes 0..7 hold x(t+1) as float2.
    float2 xr = make_float2(0.f, 0.f);
    if (warp == 17 && lane < 8)
        xr = ((const float2*)(x + ((size_t)b * TT + 1) * II))[lane];

    int pid = 0;
    unsigned par0 = 0, par1 = 0, par2 = 0;
    int cur = 0;

    // ---- Time loop (no __syncthreads; all pacing via mbarriers) ----
    for (int t = 0; t < TT; t++) {
        int nxt = cur + 1; if (nxt == 3) nxt = 0;
        if (t > 0) {
            unsigned parity = (cur == 0) ? par0 : ((cur == 1) ? par1 : par2);
            mbar_wait(sbase + OFF_MBAR_BYTES + 8 * cur, parity);
            if (cur == 0) par0 ^= 1; else if (cur == 1) par1 ^= 1; else par2 ^= 1;
        }
        const float* hxc = smf + OFF_HX + cur * HXF;
        const uint32_t nxt_f = (uint32_t)(OFF_HX + nxt * HXF);
        const uint32_t mbo   = (uint32_t)(OFF_MBAR_BYTES + 8 * nxt);

        if (tid < 512) {
            const ulonglong2* hp = (const ulonglong2*)(hxc + 36 * j);
            u64 aA = biasPack;
            u64 aB = 0;
#pragma unroll
            for (int m = 0; m < 9; m++) {
                ulonglong2 h2 = hp[m];
                aA = ffma2(w2[2 * m],     h2.x, aA);
                aB = ffma2(w2[2 * m + 1], h2.y, aB);
            }
            float a0, a1, a2, a3;
            unpack2(a0, a1, aA);
            unpack2(a2, a3, aB);
            float pre = (a0 + a1) + (a2 + a3);
            pre += __shfl_xor_sync(0xffffffffu, pre, 1);
            pre += __shfl_xor_sync(0xffffffffu, pre, 2);
            const int gate = (lane >> 2) & 3;
            float act = (gate == 2) ? ftanh(pre) : fsig(pre);
            const int b16 = lane & 16;
            float vi = __shfl_sync(0xffffffffu, act, b16);
            float vf = __shfl_sync(0xffffffffu, act, b16 + 4);
            float vg = __shfl_sync(0xffffffffu, act, b16 + 8);
            float vo = __shfl_sync(0xffffffffu, act, b16 + 12);
            float hval = 0.0f;
            if ((lane & 15) == 0) {            // lanes 0,16 own h[2*warp + (lane>>4)]
                c_state = fmaf(vf, c_state, vi * vg);
                hval = vo * ftanh(c_state);
            }
            float hodd = __shfl_sync(0xffffffffu, hval, 16);
            if (lane == 0) {
                u64 hp2 = pack2(hval, hodd);
                const uint32_t doff = (nxt_f + II + 32u * R + 2u * (uint32_t)warp) * 4u;
#pragma unroll
                for (int c = 0; c < CL; c++)
                    st_async_b64(dst4[c] + doff, hp2, dst4[c] + mbo);
            }
        } else if (warp == 16) {
            // FC for h(t-1) (in hxc) against pid captured last step; then arrive.
            const int pid_next = (int)hxc[2];     // x(t)[2]
            if (t > 0) {
                float hv = hxc[II + 32 * (int)R + lane];
                float p0 = hv * wfc0, p1 = hv * wfc1, p2 = hv * wfc2;
#pragma unroll
                for (int o = 16; o > 0; o >>= 1) {
                    p0 += __shfl_down_sync(0xffffffffu, p0, o);
                    p1 += __shfl_down_sync(0xffffffffu, p1, o);
                    p2 += __shfl_down_sync(0xffffffffu, p2, o);
                }
                if (lane == 0 && (unsigned)pid < PP) {
                    float* s = &smf[OFF_SUMS + pid * 3];
                    s[0] += p0 + bfc0; s[1] += p1 + bfc1; s[2] += p2 + bfc2;
                    if (R == 0) smf[OFF_CNT + pid] += 1.0f;
                }
            }
            pid = pid_next;
            if (lane == 0) mbar_arrive(sbase + mbo);   // after reads of hxc
        } else {
            // Comm warp: expect_tx for nxt; deliver x(t+1) to self; prefetch x(t+2).
            if (lane == 16) {
                mbar_expect_tx(sbase + mbo, TXB);
            } else if (lane < 8) {
                u64 xp = pack2(xr.x, xr.y);
                st_async_b64(sbase + (nxt_f + 2u * (uint32_t)lane) * 4u, xp, sbase + mbo);
                xr = (t + 2 < TT)
                   ? ((const float2*)(x + ((size_t)b * TT + t + 2) * II))[lane]
                   : make_float2(0.f, 0.f);
            }
        }
        cur = nxt;
    }

    // ---- Final FC round for h(TT-1): delivered into buffer 2 ----
    mbar_wait(sbase + OFF_MBAR_BYTES + 8 * 2, par2);
    if (warp == 16) {
        const float* hxc = smf + OFF_HX + 2 * HXF;
        float hv = hxc[II + 32 * (int)R + lane];
        float p0 = hv * wfc0, p1 = hv * wfc1, p2 = hv * wfc2;
#pragma unroll
        for (int o = 16; o > 0; o >>= 1) {
            p0 += __shfl_down_sync(0xffffffffu, p0, o);
            p1 += __shfl_down_sync(0xffffffffu, p1, o);
            p2 += __shfl_down_sync(0xffffffffu, p2, o);
        }
        if (lane == 0 && (unsigned)pid < PP) {
            float* s = &smf[OFF_SUMS + pid * 3];
            s[0] += p0 + bfc0; s[1] += p1 + bfc1; s[2] += p2 + bfc2;
            if (R == 0) smf[OFF_CNT + pid] += 1.0f;
        }
    }
    __syncthreads();
    asm volatile("barrier.cluster.arrive.aligned;" ::: "memory");
    asm volatile("barrier.cluster.wait.aligned;" ::: "memory");

    // ---- Epilogue: rank 0 gathers peer partial sums via DSMEM, writes out ----
    if (R == 0) {
        for (int idx = tid; idx < PP * OO; idx += NTHR) {
            float s = smf[OFF_SUMS + idx];
#pragma unroll
            for (int c = 1; c < CL; c++) {
                const uint32_t ra = pbase[c] + (uint32_t)((OFF_SUMS + idx) * 4);
                float v;
                asm volatile("ld.shared::cluster.f32 %0, [%1];" : "=f"(v) : "r"(ra));
                s += v;
            }
            const int p = idx / 3;
            float cc = smf[OFF_CNT + p];
            if (cc == 0.0f) cc = 1.0f;
            out[(size_t)b * PP * OO + idx] = s / cc;
        }
    }
    asm volatile("barrier.cluster.arrive.aligned;" ::: "memory");
    asm volatile("barrier.cluster.wait.aligned;" ::: "memory");
}

extern "C" void kernel_launch(void* const* d_in, const int* in_sizes, int n_in,
                              void* d_out, int out_size) {
    const float* x    = (const float*)d_in[0];
    const float* W_ih = (const float*)d_in[1];
    const float* W_hh = (const float*)d_in[2];
    const float* b_ih = (const float*)d_in[3];
    const float* b_hh = (const float*)d_in[4];
    const float* W_fc = (const float*)d_in[5];
    const float* b_fc = (const float*)d_in[6];
    float* out = (float*)d_out;
    lstm_nosync_kernel<<<BB * CL, NTHR>>>(x, W_ih, W_hh, b_ih, b_hh, W_fc, b_fc, out);
}

// round 10
// speedup vs baseline: 1.0911x; 1.0391x over previous
#include <cuda_runtime.h>
#include <cstdint>

// Shapes (fixed)
#define BB 32
#define TT 8192
#define II 16
#define HH 128
#define OO 3
#define PP 1024
#define CL 4
#define NTHR 576
#define HXF 160      // floats per ring slot: [0..15]=x, [16..47]=h_local, [48..143]=h_remote
#define VX 0
#define VHL 16
#define VHR 48

// Shared layout (float offsets unless noted)
#define OFF_HX 0                  // 3 * 160 = 480
#define OFF_MBAR_BYTES 1920       // bytes 1920..1943 (3 x 8B)
#define OFF_SUMS 488
#define OFF_CNT  3560
#define SMEM_FLOATS 4584
#define TXB 384u                  // 3 peers x 32 floats = 384 B per slot per phase

typedef unsigned long long u64;

__device__ __forceinline__ uint32_t smem_u32(const void* p) {
    uint32_t a;
    asm("{ .reg .u64 t; cvta.to.shared.u64 t, %1; cvt.u32.u64 %0, t; }"
        : "=r"(a) : "l"(p));
    return a;
}
__device__ __forceinline__ uint32_t mapa_u32(uint32_t a, uint32_t r) {
    uint32_t d;
    asm("mapa.shared::cluster.u32 %0, %1, %2;" : "=r"(d) : "r"(a), "r"(r));
    return d;
}
__device__ __forceinline__ void mbar_init(uint32_t mbar, uint32_t cnt) {
    asm volatile("mbarrier.init.shared.b64 [%0], %1;" :: "r"(mbar), "r"(cnt) : "memory");
}
__device__ __forceinline__ void mbar_expect_tx(uint32_t mbar, uint32_t tx) {
    asm volatile("mbarrier.arrive.expect_tx.shared.b64 _, [%0], %1;"
                 :: "r"(mbar), "r"(tx) : "memory");
}
__device__ __forceinline__ void mbar_wait(uint32_t mbar, unsigned parity) {
    asm volatile(
        "{\n\t.reg .pred P;\n"
        "W%=:\n\t"
        "mbarrier.try_wait.parity.acquire.cta.shared::cta.b64 P, [%0], %1, 10000000;\n\t"
        "@!P bra W%=;\n\t"
        "}" :: "r"(mbar), "r"(parity) : "memory");
}
__device__ __forceinline__ void st_async_b64(uint32_t addr, u64 v, uint32_t mbar) {
    asm volatile("st.async.shared::cluster.mbarrier::complete_tx::bytes.b64 [%0], %1, [%2];"
                 :: "r"(addr), "l"(v), "r"(mbar) : "memory");
}
__device__ __forceinline__ u64 pack2(float lo, float hi) {
    u64 p;
    asm("mov.b64 %0, {%1, %2};" : "=l"(p) : "r"(__float_as_uint(lo)), "r"(__float_as_uint(hi)));
    return p;
}
__device__ __forceinline__ void unpack2(float& lo, float& hi, u64 p) {
    uint32_t a, b;
    asm("mov.b64 {%0, %1}, %2;" : "=r"(a), "=r"(b) : "l"(p));
    lo = __uint_as_float(a); hi = __uint_as_float(b);
}
__device__ __forceinline__ u64 ffma2(u64 a, u64 b, u64 c) {
    u64 d;
    asm("fma.rn.f32x2 %0, %1, %2, %3;" : "=l"(d) : "l"(a), "l"(b), "l"(c));
    return d;
}
__device__ __forceinline__ float fsig(float v)  { return __fdividef(1.0f, 1.0f + __expf(-v)); }
__device__ __forceinline__ float ftanh(float v) { return 2.0f * __fdividef(1.0f, 1.0f + __expf(-2.0f * v)) - 1.0f; }

__global__ void __launch_bounds__(NTHR, 1) __cluster_dims__(CL, 1, 1)
lstm_shadow_kernel(const float* __restrict__ x,
                   const float* __restrict__ W_ih,
                   const float* __restrict__ W_hh,
                   const float* __restrict__ b_ih,
                   const float* __restrict__ b_hh,
                   const float* __restrict__ W_fc,
                   const float* __restrict__ b_fc,
                   float* __restrict__ out) {
    __shared__ __align__(16) float smf[SMEM_FLOATS];
    const int tid  = threadIdx.x;
    const int warp = tid >> 5;
    const int lane = tid & 31;
    uint32_t R;
    asm("mov.u32 %0, %%cluster_ctarank;" : "=r"(R));
    const int b = blockIdx.x >> 2;

    const uint32_t sbase = smem_u32(smf);
    uint32_t pbase[CL];
#pragma unroll
    for (int c = 0; c < CL; c++) pbase[c] = mapa_u32(sbase, (uint32_t)c);

    // ---- Prologue: accumulators, barriers, slot 0 = [x(0) | zeros] ----
    for (int i = tid; i < PP * OO; i += NTHR) smf[OFF_SUMS + i] = 0.0f;
    for (int i = tid; i < PP; i += NTHR)      smf[OFF_CNT + i]  = 0.0f;
    if (tid == 0) {
#pragma unroll
        for (int s = 0; s < 3; s++) mbar_init(sbase + OFF_MBAR_BYTES + 8 * s, 1);
    }
    if (tid < II)                    smf[OFF_HX + VX + tid]  = x[((size_t)b * TT) * II + tid];
    if (tid >= II && tid < HXF - 16) smf[OFF_HX + tid]       = 0.0f;   // h_local+h_remote = 0
    __syncthreads();
    asm volatile("barrier.cluster.arrive.aligned;" ::: "memory");
    asm volatile("barrier.cluster.wait.aligned;" ::: "memory");

    // ---- Matvec role prologue ----
    // lane = rowhalf*16 + gate*4 + j ; hl2 = 2*warp + rowhalf ; row = gate*128 + 32R + hl2.
    // Thread j covers local v[12j..12j+12) and remote v[48+24j..48+24j+24).
    u64   w2l[6], w2r[12];
    u64   biasPack = 0, aLA = 0, aLB = 0;
    float c_state = 0.0f;
    int   j = 0;
    uint32_t peerh[3], peerm[3];
    if (tid < 512) {
        j = lane & 3;
        const int gate = (lane >> 2) & 3;
        const int hl2  = 2 * warp + (lane >> 4);
        const int row  = gate * HH + 32 * (int)R + hl2;
        float wl[12], wr[24];
#pragma unroll
        for (int m = 0; m < 12; m++) {
            const int p = 12 * j + m;
            wl[m] = (p < 16) ? W_ih[(size_t)row * II + p]
                             : W_hh[(size_t)row * HH + 32 * (int)R + (p - 16)];
        }
#pragma unroll
        for (int m = 0; m < 24; m++) {
            const int q = 24 * j + m;
            int sr = q >> 5;                       // sender slot index 0..2
            const int r = (sr < (int)R) ? sr : sr + 1;  // actual sender rank
            wr[m] = W_hh[(size_t)row * HH + 32 * r + (q & 31)];
        }
#pragma unroll
        for (int m = 0; m < 6; m++)  w2l[m] = pack2(wl[2 * m], wl[2 * m + 1]);
#pragma unroll
        for (int m = 0; m < 12; m++) w2r[m] = pack2(wr[2 * m], wr[2 * m + 1]);
        if (j == 0) biasPack = pack2(b_ih[row] + b_hh[row], 0.0f);
        // owner (lane==0) send targets: my 32-block lands at peer's VHR + 32*idx
        if (lane == 0) {
#pragma unroll
            for (int c3 = 0; c3 < 3; c3++) {
                const int c  = (int)((R + 1 + c3) & 3);
                const int ix = ((int)R < c) ? (int)R : (int)R - 1;
                peerh[c3] = pbase[c] + (uint32_t)((OFF_HX + VHR + 32 * ix + 2 * warp) * 4);
                peerm[c3] = pbase[c] + OFF_MBAR_BYTES;
            }
        }
        // Pre-loop: local partial for step 0 over slot 0 (x(0), h_local=0)
        const ulonglong2* hlp = (const ulonglong2*)(smf + OFF_HX + 12 * j);
        u64 aA = biasPack, aB = 0;
#pragma unroll
        for (int m = 0; m < 3; m++) {
            ulonglong2 h2 = hlp[m];
            aA = ffma2(w2l[2 * m],     h2.x, aA);
            aB = ffma2(w2l[2 * m + 1], h2.y, aB);
        }
        aLA = aA; aLB = aB;
    }
    // FC warp (16)
    float wfc0 = 0.f, wfc1 = 0.f, wfc2 = 0.f, bfc0 = 0.f, bfc1 = 0.f, bfc2 = 0.f;
    if (warp == 16) {
        const int hi = 32 * (int)R + lane;
        wfc0 = W_fc[hi]; wfc1 = W_fc[HH + hi]; wfc2 = W_fc[2 * HH + hi];
        if (R == 0 && lane == 0) { bfc0 = b_fc[0]; bfc1 = b_fc[1]; bfc2 = b_fc[2]; }
    }
    // Comm warp (17): lanes 0..7 hold x(t+1) as float2
    float2 xr = make_float2(0.f, 0.f);
    if (warp == 17 && lane < 8)
        xr = ((const float2*)(x + ((size_t)b * TT + 1) * II))[lane];

    int pid = 0;
    unsigned par0 = 0, par1 = 0, par2 = 0;
    int cur = 0;

    // ---- Time loop ----
    for (int t = 0; t < TT; t++) {
        int nxt = cur + 1; if (nxt == 3) nxt = 0;
        const float* hxc = smf + OFF_HX + cur * HXF;
        const uint32_t mbo = (uint32_t)(OFF_MBAR_BYTES + 8 * nxt);

        if (tid < 512) {
            if (t > 0) {
                unsigned parity = (cur == 0) ? par0 : ((cur == 1) ? par1 : par2);
                mbar_wait(sbase + OFF_MBAR_BYTES + 8 * cur, parity);
                if (cur == 0) par0 ^= 1; else if (cur == 1) par1 ^= 1; else par2 ^= 1;
            }
            // Remote dot (96 wide) on top of saved local partial
            u64 aA = aLA, aB = aLB;
            const ulonglong2* hr = (const ulonglong2*)(hxc + VHR + 24 * j);
#pragma unroll
            for (int m = 0; m < 6; m++) {
                ulonglong2 h2 = hr[m];
                aA = ffma2(w2r[2 * m],     h2.x, aA);
                aB = ffma2(w2r[2 * m + 1], h2.y, aB);
            }
            float a0, a1, a2, a3;
            unpack2(a0, a1, aA);
            unpack2(a2, a3, aB);
            float pre = (a0 + a1) + (a2 + a3);
            pre += __shfl_xor_sync(0xffffffffu, pre, 1);
            pre += __shfl_xor_sync(0xffffffffu, pre, 2);
            const int gate = (lane >> 2) & 3;
            float act = (gate == 2) ? ftanh(pre) : fsig(pre);
            const int b16 = lane & 16;
            float vi = __shfl_sync(0xffffffffu, act, b16);
            float vf = __shfl_sync(0xffffffffu, act, b16 + 4);
            float vg = __shfl_sync(0xffffffffu, act, b16 + 8);
            float vo = __shfl_sync(0xffffffffu, act, b16 + 12);
            float hval = 0.0f;
            if ((lane & 15) == 0) {            // lanes 0,16 own h[2*warp + (lane>>4)]
                c_state = fmaf(vf, c_state, vi * vg);
                hval = vo * ftanh(c_state);
            }
            float hodd = __shfl_sync(0xffffffffu, hval, 16);
            if (lane == 0) {
                u64 hp2 = pack2(hval, hodd);
                const uint32_t slotB = (uint32_t)(nxt * HXF * 4);
#pragma unroll
                for (int c3 = 0; c3 < 3; c3++)
                    st_async_b64(peerh[c3] + slotB, hp2, peerm[c3] + 8 * nxt);
                // local h_local STS (generic; ordered by the syncthreads below)
                *(u64*)((char*)smf + (OFF_HX + VHL + 2 * warp) * 4 + slotB) = hp2;
            }
        } else if (warp == 16) {
            // FC for h(t-1): slot cur local region; pid captured last step from x(t-1)[2]
            const int pid_next = (int)hxc[VX + 2];    // x(t)[2]
            if (t > 0) {
                float hv = hxc[VHL + lane];
                float p0 = hv * wfc0, p1 = hv * wfc1, p2 = hv * wfc2;
#pragma unroll
                for (int o = 16; o > 0; o >>= 1) {
                    p0 += __shfl_down_sync(0xffffffffu, p0, o);
                    p1 += __shfl_down_sync(0xffffffffu, p1, o);
                    p2 += __shfl_down_sync(0xffffffffu, p2, o);
                }
                if (lane == 0 && (unsigned)pid < PP) {
                    float* s = &smf[OFF_SUMS + pid * 3];
                    s[0] += p0 + bfc0; s[1] += p1 + bfc1; s[2] += p2 + bfc2;
                    if (R == 0) smf[OFF_CNT + pid] += 1.0f;
                }
            }
            pid = pid_next;
        } else {
            // Comm warp: x(t+1) into slot nxt (plain STS), expect_tx(nxt), prefetch x(t+2)
            if (lane == 16) {
                mbar_expect_tx(sbase + mbo, TXB);
            } else if (lane < 8) {
                *(float2*)&smf[OFF_HX + nxt * HXF + VX + 2 * lane] = xr;
                xr = (t + 2 < TT)
                   ? ((const float2*)(x + ((size_t)b * TT + t + 2) * II))[lane]
                   : make_float2(0.f, 0.f);
            }
        }
        __syncthreads();
        // Shadow work: local partial dot for step t+1 over slot nxt [x(t+1) | h_local(t)]
        if (tid < 512) {
            const ulonglong2* hlp = (const ulonglong2*)(smf + OFF_HX + nxt * HXF + 12 * j);
            u64 aA = biasPack, aB = 0;
#pragma unroll
            for (int m = 0; m < 3; m++) {
                ulonglong2 h2 = hlp[m];
                aA = ffma2(w2l[2 * m],     h2.x, aA);
                aB = ffma2(w2l[2 * m + 1], h2.y, aB);
            }
            aLA = aA; aLB = aB;
        }
        cur = nxt;
    }

    // ---- Final FC round for h(TT-1): slot 2 local region (8191%3==1 -> nxt==2) ----
    if (warp == 16) {
        const float* hxc = smf + OFF_HX + 2 * HXF;
        float hv = hxc[VHL + lane];
        float p0 = hv * wfc0, p1 = hv * wfc1, p2 = hv * wfc2;
#pragma unroll
        for (int o = 16; o > 0; o >>= 1) {
            p0 += __shfl_down_sync(0xffffffffu, p0, o);
            p1 += __shfl_down_sync(0xffffffffu, p1, o);
            p2 += __shfl_down_sync(0xffffffffu, p2, o);
        }
        if (lane == 0 && (unsigned)pid < PP) {
            float* s = &smf[OFF_SUMS + pid * 3];
            s[0] += p0 + bfc0; s[1] += p1 + bfc1; s[2] += p2 + bfc2;
            if (R == 0) smf[OFF_CNT + pid] += 1.0f;
        }
    }
    __syncthreads();
    asm volatile("barrier.cluster.arrive.aligned;" ::: "memory");
    asm volatile("barrier.cluster.wait.aligned;" ::: "memory");

    // ---- Epilogue: rank 0 gathers peer partial sums via DSMEM, writes out ----
    if (R == 0) {
        for (int idx = tid; idx < PP * OO; idx += NTHR) {
            float s = smf[OFF_SUMS + idx];
#pragma unroll
            for (int c = 1; c < CL; c++) {
                const uint32_t ra = pbase[c] + (uint32_t)((OFF_SUMS + idx) * 4);
                float v;
                asm volatile("ld.shared::cluster.f32 %0, [%1];" : "=f"(v) : "r"(ra));
                s += v;
            }
            const int p = idx / 3;
            float cc = smf[OFF_CNT + p];
            if (cc == 0.0f) cc = 1.0f;
            out[(size_t)b * PP * OO + idx] = s / cc;
        }
    }
    asm volatile("barrier.cluster.arrive.aligned;" ::: "memory");
    asm volatile("barrier.cluster.wait.aligned;" ::: "memory");
}

extern "C" void kernel_launch(void* const* d_in, const int* in_sizes, int n_in,
                              void* d_out, int out_size) {
    const float* x    = (const float*)d_in[0];
    const float* W_ih = (const float*)d_in[1];
    const float* W_hh = (const float*)d_in[2];
    const float* b_ih = (const float*)d_in[3];
    const float* b_hh = (const float*)d_in[4];
    const float* W_fc = (const float*)d_in[5];
    const float* b_fc = (const float*)d_in[6];
    float* out = (float*)d_out;
    lstm_shadow_kernel<<<BB * CL, NTHR>>>(x, W_ih, W_hh, b_ih, b_hh, W_fc, b_fc, out);
}

// round 11
// speedup vs baseline: 1.0920x; 1.0008x over previous
#include <cuda_runtime.h>
#include <cstdint>

// Shapes (fixed)
#define BB 32
#define TT 8192
#define II 16
#define HH 128
#define OO 3
#define PP 1024
#define CL 4
#define NTHR 576
#define HXF 160      // floats per ring slot: [0..15]=x, [16..47]=h_local, [48..143]=h_remote
#define VX 0
#define VHL 16
#define VHR 48

// Shared layout (float offsets unless noted)
#define OFF_HX 0                  // 3 * 160 = 480
#define OFF_MBAR_BYTES 1920       // bytes 1920..1943 (3 x 8B)
#define OFF_SUMS 488
#define OFF_CNT  3560
#define SMEM_FLOATS 4584
#define TXB 384u                  // 3 peers x 32 floats = 384 B per slot per phase

typedef unsigned long long u64;

__device__ __forceinline__ uint32_t smem_u32(const void* p) {
    uint32_t a;
    asm("{ .reg .u64 t; cvta.to.shared.u64 t, %1; cvt.u32.u64 %0, t; }"
        : "=r"(a) : "l"(p));
    return a;
}
__device__ __forceinline__ uint32_t mapa_u32(uint32_t a, uint32_t r) {
    uint32_t d;
    asm("mapa.shared::cluster.u32 %0, %1, %2;" : "=r"(d) : "r"(a), "r"(r));
    return d;
}
__device__ __forceinline__ void mbar_init(uint32_t mbar, uint32_t cnt) {
    asm volatile("mbarrier.init.shared.b64 [%0], %1;" :: "r"(mbar), "r"(cnt) : "memory");
}
__device__ __forceinline__ void mbar_expect_tx(uint32_t mbar, uint32_t tx) {
    asm volatile("mbarrier.arrive.expect_tx.shared.b64 _, [%0], %1;"
                 :: "r"(mbar), "r"(tx) : "memory");
}
__device__ __forceinline__ void mbar_wait(uint32_t mbar, unsigned parity) {
    asm volatile(
        "{\n\t.reg .pred P;\n"
        "W%=:\n\t"
        "mbarrier.try_wait.parity.acquire.cta.shared::cta.b64 P, [%0], %1, 10000000;\n\t"
        "@!P bra W%=;\n\t"
        "}" :: "r"(mbar), "r"(parity) : "memory");
}
__device__ __forceinline__ void st_async_b64(uint32_t addr, u64 v, uint32_t mbar) {
    asm volatile("st.async.shared::cluster.mbarrier::complete_tx::bytes.b64 [%0], %1, [%2];"
                 :: "r"(addr), "l"(v), "r"(mbar) : "memory");
}
__device__ __forceinline__ u64 pack2(float lo, float hi) {
    u64 p;
    asm("mov.b64 %0, {%1, %2};" : "=l"(p) : "r"(__float_as_uint(lo)), "r"(__float_as_uint(hi)));
    return p;
}
__device__ __forceinline__ void unpack2(float& lo, float& hi, u64 p) {
    uint32_t a, b;
    asm("mov.b64 {%0, %1}, %2;" : "=r"(a), "=r"(b) : "l"(p));
    lo = __uint_as_float(a); hi = __uint_as_float(b);
}
__device__ __forceinline__ u64 ffma2(u64 a, u64 b, u64 c) {
    u64 d;
    asm("fma.rn.f32x2 %0, %1, %2, %3;" : "=l"(d) : "l"(a), "l"(b), "l"(c));
    return d;
}
__device__ __forceinline__ float fsig(float v)  { return __fdividef(1.0f, 1.0f + __expf(-v)); }
__device__ __forceinline__ float ftanh(float v) { return 2.0f * __fdividef(1.0f, 1.0f + __expf(-2.0f * v)) - 1.0f; }

__global__ void __launch_bounds__(NTHR, 1) __cluster_dims__(CL, 1, 1)
lstm_shadow_kernel(const float* __restrict__ x,
                   const float* __restrict__ W_ih,
                   const float* __restrict__ W_hh,
                   const float* __restrict__ b_ih,
                   const float* __restrict__ b_hh,
                   const float* __restrict__ W_fc,
                   const float* __restrict__ b_fc,
                   float* __restrict__ out) {
    __shared__ __align__(16) float smf[SMEM_FLOATS];
    const int tid  = threadIdx.x;
    const int warp = tid >> 5;
    const int lane = tid & 31;
    uint32_t R;
    asm("mov.u32 %0, %%cluster_ctarank;" : "=r"(R));
    const int b = blockIdx.x >> 2;

    const uint32_t sbase = smem_u32(smf);
    uint32_t pbase[CL];
#pragma unroll
    for (int c = 0; c < CL; c++) pbase[c] = mapa_u32(sbase, (uint32_t)c);

    // ---- Prologue: accumulators, barriers, slot 0 = [x(0) | zeros] ----
    for (int i = tid; i < PP * OO; i += NTHR) smf[OFF_SUMS + i] = 0.0f;
    for (int i = tid; i < PP; i += NTHR)      smf[OFF_CNT + i]  = 0.0f;
    if (tid == 0) {
#pragma unroll
        for (int s = 0; s < 3; s++) mbar_init(sbase + OFF_MBAR_BYTES + 8 * s, 1);
    }
    if (tid < II)                    smf[OFF_HX + VX + tid]  = x[((size_t)b * TT) * II + tid];
    if (tid >= II && tid < HXF - 16) smf[OFF_HX + tid]       = 0.0f;   // h_local+h_remote = 0
    __syncthreads();
    asm volatile("barrier.cluster.arrive.aligned;" ::: "memory");
    asm volatile("barrier.cluster.wait.aligned;" ::: "memory");

    // ---- Matvec role prologue ----
    // lane = rowhalf*16 + gate*4 + j ; hl2 = 2*warp + rowhalf ; row = gate*128 + 32R + hl2.
    // Thread j covers local v[12j..12j+12) and remote v[48+24j..48+24j+24).
    u64   w2l[6], w2r[12];
    u64   biasPack = 0, aLA = 0, aLB = 0;
    float c_state = 0.0f;
    int   j = 0;
    uint32_t peerh[3], peerm[3];
    if (tid < 512) {
        j = lane & 3;
        const int gate = (lane >> 2) & 3;
        const int hl2  = 2 * warp + (lane >> 4);
        const int row  = gate * HH + 32 * (int)R + hl2;
        float wl[12], wr[24];
#pragma unroll
        for (int m = 0; m < 12; m++) {
            const int p = 12 * j + m;
            wl[m] = (p < 16) ? W_ih[(size_t)row * II + p]
                             : W_hh[(size_t)row * HH + 32 * (int)R + (p - 16)];
        }
#pragma unroll
        for (int m = 0; m < 24; m++) {
            const int q = 24 * j + m;
            int sr = q >> 5;                       // sender slot index 0..2
            const int r = (sr < (int)R) ? sr : sr + 1;  // actual sender rank
            wr[m] = W_hh[(size_t)row * HH + 32 * r + (q & 31)];
        }
#pragma unroll
        for (int m = 0; m < 6; m++)  w2l[m] = pack2(wl[2 * m], wl[2 * m + 1]);
#pragma unroll
        for (int m = 0; m < 12; m++) w2r[m] = pack2(wr[2 * m], wr[2 * m + 1]);
        if (j == 0) biasPack = pack2(b_ih[row] + b_hh[row], 0.0f);
        // owner (lane==0) send targets: my 32-block lands at peer's VHR + 32*idx
        if (lane == 0) {
#pragma unroll
            for (int c3 = 0; c3 < 3; c3++) {
                const int c  = (int)((R + 1 + c3) & 3);
                const int ix = ((int)R < c) ? (int)R : (int)R - 1;
                peerh[c3] = pbase[c] + (uint32_t)((OFF_HX + VHR + 32 * ix + 2 * warp) * 4);
                peerm[c3] = pbase[c] + OFF_MBAR_BYTES;
            }
        }
        // Pre-loop: local partial for step 0 over slot 0 (x(0), h_local=0)
        const ulonglong2* hlp = (const ulonglong2*)(smf + OFF_HX + 12 * j);
        u64 aA = biasPack, aB = 0;
#pragma unroll
        for (int m = 0; m < 3; m++) {
            ulonglong2 h2 = hlp[m];
            aA = ffma2(w2l[2 * m],     h2.x, aA);
            aB = ffma2(w2l[2 * m + 1], h2.y, aB);
        }
        aLA = aA; aLB = aB;
    }
    // FC warp (16)
    float wfc0 = 0.f, wfc1 = 0.f, wfc2 = 0.f, bfc0 = 0.f, bfc1 = 0.f, bfc2 = 0.f;
    if (warp == 16) {
        const int hi = 32 * (int)R + lane;
        wfc0 = W_fc[hi]; wfc1 = W_fc[HH + hi]; wfc2 = W_fc[2 * HH + hi];
        if (R == 0 && lane == 0) { bfc0 = b_fc[0]; bfc1 = b_fc[1]; bfc2 = b_fc[2]; }
    }
    // Comm warp (17): lanes 0..7 hold x(t+1) as float2
    float2 xr = make_float2(0.f, 0.f);
    if (warp == 17 && lane < 8)
        xr = ((const float2*)(x + ((size_t)b * TT + 1) * II))[lane];

    int pid = 0;
    unsigned par0 = 0, par1 = 0, par2 = 0;
    int cur = 0;

    // ---- Time loop ----
    for (int t = 0; t < TT; t++) {
        int nxt = cur + 1; if (nxt == 3) nxt = 0;
        const float* hxc = smf + OFF_HX + cur * HXF;
        const uint32_t mbo = (uint32_t)(OFF_MBAR_BYTES + 8 * nxt);

        if (tid < 512) {
            if (t > 0) {
                unsigned parity = (cur == 0) ? par0 : ((cur == 1) ? par1 : par2);
                mbar_wait(sbase + OFF_MBAR_BYTES + 8 * cur, parity);
                if (cur == 0) par0 ^= 1; else if (cur == 1) par1 ^= 1; else par2 ^= 1;
            }
            // Remote dot (96 wide) on top of saved local partial
            u64 aA = aLA, aB = aLB;
            const ulonglong2* hr = (const ulonglong2*)(hxc + VHR + 24 * j);
#pragma unroll
            for (int m = 0; m < 6; m++) {
                ulonglong2 h2 = hr[m];
                aA = ffma2(w2r[2 * m],     h2.x, aA);
                aB = ffma2(w2r[2 * m + 1], h2.y, aB);
            }
            float a0, a1, a2, a3;
            unpack2(a0, a1, aA);
            unpack2(a2, a3, aB);
            float pre = (a0 + a1) + (a2 + a3);
            pre += __shfl_xor_sync(0xffffffffu, pre, 1);
            pre += __shfl_xor_sync(0xffffffffu, pre, 2);
            const int gate = (lane >> 2) & 3;
            float act = (gate == 2) ? ftanh(pre) : fsig(pre);
            const int b16 = lane & 16;
            float vi = __shfl_sync(0xffffffffu, act, b16);
            float vf = __shfl_sync(0xffffffffu, act, b16 + 4);
            float vg = __shfl_sync(0xffffffffu, act, b16 + 8);
            float vo = __shfl_sync(0xffffffffu, act, b16 + 12);
            float hval = 0.0f;
            if ((lane & 15) == 0) {            // lanes 0,16 own h[2*warp + (lane>>4)]
                c_state = fmaf(vf, c_state, vi * vg);
                hval = vo * ftanh(c_state);
            }
            float hodd = __shfl_sync(0xffffffffu, hval, 16);
            if (lane == 0) {
                u64 hp2 = pack2(hval, hodd);
                const uint32_t slotB = (uint32_t)(nxt * HXF * 4);
#pragma unroll
                for (int c3 = 0; c3 < 3; c3++)
                    st_async_b64(peerh[c3] + slotB, hp2, peerm[c3] + 8 * nxt);
                // local h_local STS (generic; ordered by the syncthreads below)
                *(u64*)((char*)smf + (OFF_HX + VHL + 2 * warp) * 4 + slotB) = hp2;
            }
        } else if (warp == 16) {
            // FC for h(t-1): slot cur local region; pid captured last step from x(t-1)[2]
            const int pid_next = (int)hxc[VX + 2];    // x(t)[2]
            if (t > 0) {
                float hv = hxc[VHL + lane];
                float p0 = hv * wfc0, p1 = hv * wfc1, p2 = hv * wfc2;
#pragma unroll
                for (int o = 16; o > 0; o >>= 1) {
                    p0 += __shfl_down_sync(0xffffffffu, p0, o);
                    p1 += __shfl_down_sync(0xffffffffu, p1, o);
                    p2 += __shfl_down_sync(0xffffffffu, p2, o);
                }
                if (lane == 0 && (unsigned)pid < PP) {
                    float* s = &smf[OFF_SUMS + pid * 3];
                    s[0] += p0 + bfc0; s[1] += p1 + bfc1; s[2] += p2 + bfc2;
                    if (R == 0) smf[OFF_CNT + pid] += 1.0f;
                }
            }
            pid = pid_next;
        } else {
            // Comm warp: x(t+1) into slot nxt (plain STS), expect_tx(nxt), prefetch x(t+2)
            if (lane == 16) {
                mbar_expect_tx(sbase + mbo, TXB);
            } else if (lane < 8) {
                *(float2*)&smf[OFF_HX + nxt * HXF + VX + 2 * lane] = xr;
                xr = (t + 2 < TT)
                   ? ((const float2*)(x + ((size_t)b * TT + t + 2) * II))[lane]
                   : make_float2(0.f, 0.f);
            }
        }
        __syncthreads();
        // Shadow work: local partial dot for step t+1 over slot nxt [x(t+1) | h_local(t)]
        if (tid < 512) {
            const ulonglong2* hlp = (const ulonglong2*)(smf + OFF_HX + nxt * HXF + 12 * j);
            u64 aA = biasPack, aB = 0;
#pragma unroll
            for (int m = 0; m < 3; m++) {
                ulonglong2 h2 = hlp[m];
                aA = ffma2(w2l[2 * m],     h2.x, aA);
                aB = ffma2(w2l[2 * m + 1], h2.y, aB);
            }
            aLA = aA; aLB = aB;
        }
        cur = nxt;
    }

    // ---- Final FC round for h(TT-1): slot 2 local region (8191%3==1 -> nxt==2) ----
    if (warp == 16) {
        const float* hxc = smf + OFF_HX + 2 * HXF;
        float hv = hxc[VHL + lane];
        float p0 = hv * wfc0, p1 = hv * wfc1, p2 = hv * wfc2;
#pragma unroll
        for (int o = 16; o > 0; o >>= 1) {
            p0 += __shfl_down_sync(0xffffffffu, p0, o);
            p1 += __shfl_down_sync(0xffffffffu, p1, o);
            p2 += __shfl_down_sync(0xffffffffu, p2, o);
        }
        if (lane == 0 && (unsigned)pid < PP) {
            float* s = &smf[OFF_SUMS + pid * 3];
            s[0] += p0 + bfc0; s[1] += p1 + bfc1; s[2] += p2 + bfc2;
            if (R == 0) smf[OFF_CNT + pid] += 1.0f;
        }
    }
    __syncthreads();
    asm volatile("barrier.cluster.arrive.aligned;" ::: "memory");
    asm volatile("barrier.cluster.wait.aligned;" ::: "memory");

    // ---- Epilogue: rank 0 gathers peer partial sums via DSMEM, writes out ----
    if (R == 0) {
        for (int idx = tid; idx < PP * OO; idx += NTHR) {
            float s = smf[OFF_SUMS + idx];
#pragma unroll
            for (int c = 1; c < CL; c++) {
                const uint32_t ra = pbase[c] + (uint32_t)((OFF_SUMS + idx) * 4);
                float v;
                asm volatile("ld.shared::cluster.f32 %0, [%1];" : "=f"(v) : "r"(ra));
                s += v;
            }
            const int p = idx / 3;
            float cc = smf[OFF_CNT + p];
            if (cc == 0.0f) cc = 1.0f;
            out[(size_t)b * PP * OO + idx] = s / cc;
        }
    }
    asm volatile("barrier.cluster.arrive.aligned;" ::: "memory");
    asm volatile("barrier.cluster.wait.aligned;" ::: "memory");
}

extern "C" void kernel_launch(void* const* d_in, const int* in_sizes, int n_in,
                              void* d_out, int out_size) {
    const float* x    = (const float*)d_in[0];
    const float* W_ih = (const float*)d_in[1];
    const float* W_hh = (const float*)d_in[2];
    const float* b_ih = (const float*)d_in[3];
    const float* b_hh = (const float*)d_in[4];
    const float* W_fc = (const float*)d_in[5];
    const float* b_fc = (const float*)d_in[6];
    float* out = (float*)d_out;
    lstm_shadow_kernel<<<BB * CL, NTHR>>>(x, W_ih, W_hh, b_ih, b_hh, W_fc, b_fc, out);
}

// round 12
// speedup vs baseline: 1.3563x; 1.2421x over previous
#include <cuda_runtime.h>
#include <cstdint>

// Shapes (fixed)
#define BB 32
#define TT 8192
#define II 16
#define HH 128
#define OO 3
#define PP 1024
#define CL 4
#define NTHR 576
#define HXF 160      // floats per ring slot: [0..15]=x, [16..47]=h_local, [48..143]=h_remote
#define VX 0
#define VHL 16
#define VHR 48

// Shared layout (float offsets unless noted)
#define OFF_HX 0                  // 3 * 160 = 480
#define OFF_MBAR_BYTES 1920       // bytes 1920..1943 (3 x 8B)
#define OFF_SUMS 488
#define OFF_CNT  3560
#define SMEM_FLOATS 4584
#define TXB 384u                  // 3 peers x 32 floats = 384 B per slot per phase

typedef unsigned long long u64;

__device__ __forceinline__ uint32_t smem_u32(const void* p) {
    uint32_t a;
    asm("{ .reg .u64 t; cvta.to.shared.u64 t, %1; cvt.u32.u64 %0, t; }"
        : "=r"(a) : "l"(p));
    return a;
}
__device__ __forceinline__ uint32_t mapa_u32(uint32_t a, uint32_t r) {
    uint32_t d;
    asm("mapa.shared::cluster.u32 %0, %1, %2;" : "=r"(d) : "r"(a), "r"(r));
    return d;
}
__device__ __forceinline__ void mbar_init(uint32_t mbar, uint32_t cnt) {
    asm volatile("mbarrier.init.shared.b64 [%0], %1;" :: "r"(mbar), "r"(cnt) : "memory");
}
__device__ __forceinline__ void mbar_expect_tx(uint32_t mbar, uint32_t tx) {
    asm volatile("mbarrier.arrive.expect_tx.shared.b64 _, [%0], %1;"
                 :: "r"(mbar), "r"(tx) : "memory");
}
__device__ __forceinline__ void mbar_wait(uint32_t mbar, unsigned parity) {
    asm volatile(
        "{\n\t.reg .pred P;\n"
        "W%=:\n\t"
        "mbarrier.try_wait.parity.acquire.cta.shared::cta.b64 P, [%0], %1, 10000000;\n\t"
        "@!P bra W%=;\n\t"
        "}" :: "r"(mbar), "r"(parity) : "memory");
}
__device__ __forceinline__ void st_async_b32(uint32_t addr, float v, uint32_t mbar) {
    asm volatile("st.async.shared::cluster.mbarrier::complete_tx::bytes.b32 [%0], %1, [%2];"
                 :: "r"(addr), "r"(__float_as_uint(v)), "r"(mbar) : "memory");
}
__device__ __forceinline__ u64 pack2(float lo, float hi) {
    u64 p;
    asm("mov.b64 %0, {%1, %2};" : "=l"(p) : "r"(__float_as_uint(lo)), "r"(__float_as_uint(hi)));
    return p;
}
__device__ __forceinline__ void unpack2(float& lo, float& hi, u64 p) {
    uint32_t a, b;
    asm("mov.b64 {%0, %1}, %2;" : "=r"(a), "=r"(b) : "l"(p));
    lo = __uint_as_float(a); hi = __uint_as_float(b);
}
__device__ __forceinline__ u64 ffma2(u64 a, u64 b, u64 c) {
    u64 d;
    asm("fma.rn.f32x2 %0, %1, %2, %3;" : "=l"(d) : "l"(a), "l"(b), "l"(c));
    return d;
}
// HW tanh (MUFU.TANH, 1 MUFU op)
__device__ __forceinline__ float tanh_ap(float v) {
    float y;
    asm("tanh.approx.f32 %0, %1;" : "=f"(y) : "f"(v));
    return y;
}
// sigmoid(x) = 0.5*tanh(0.5x) + 0.5
__device__ __forceinline__ float sig_ap(float v) {
    return fmaf(0.5f, tanh_ap(0.5f * v), 0.5f);
}

__global__ void __launch_bounds__(NTHR, 1) __cluster_dims__(CL, 1, 1)
lstm_tanhhw_kernel(const float* __restrict__ x,
                   const float* __restrict__ W_ih,
                   const float* __restrict__ W_hh,
                   const float* __restrict__ b_ih,
                   const float* __restrict__ b_hh,
                   const float* __restrict__ W_fc,
                   const float* __restrict__ b_fc,
                   float* __restrict__ out) {
    __shared__ __align__(16) float smf[SMEM_FLOATS];
    const int tid  = threadIdx.x;
    const int warp = tid >> 5;
    const int lane = tid & 31;
    uint32_t R;
    asm("mov.u32 %0, %%cluster_ctarank;" : "=r"(R));
    const int b = blockIdx.x >> 2;

    const uint32_t sbase = smem_u32(smf);
    uint32_t pbase[CL];
#pragma unroll
    for (int c = 0; c < CL; c++) pbase[c] = mapa_u32(sbase, (uint32_t)c);

    // ---- Prologue: accumulators, barriers, slot 0 = [x(0) | zeros] ----
    for (int i = tid; i < PP * OO; i += NTHR) smf[OFF_SUMS + i] = 0.0f;
    for (int i = tid; i < PP; i += NTHR)      smf[OFF_CNT + i]  = 0.0f;
    if (tid == 0) {
#pragma unroll
        for (int s = 0; s < 3; s++) mbar_init(sbase + OFF_MBAR_BYTES + 8 * s, 1);
    }
    if (tid < II)                    smf[OFF_HX + VX + tid]  = x[((size_t)b * TT) * II + tid];
    if (tid >= II && tid < HXF - 16) smf[OFF_HX + tid]       = 0.0f;   // h_local+h_remote = 0
    __syncthreads();
    asm volatile("barrier.cluster.arrive.aligned;" ::: "memory");
    asm volatile("barrier.cluster.wait.aligned;" ::: "memory");

    // ---- Matvec role prologue ----
    // lane = rowhalf*16 + gate*4 + j ; hl2 = 2*warp + rowhalf ; row = gate*128 + 32R + hl2.
    // Thread j covers local v[12j..12j+12) and remote v[48+24j..48+24j+24).
    u64   w2l[6], w2r[12];
    u64   biasPack = 0, aLA = 0, aLB = 0;
    float c_state = 0.0f;
    int   j = 0;
    uint32_t peerh[3], peerm[3];
    const bool owner = (tid < 512) && ((lane & 15) == 0);
    if (tid < 512) {
        j = lane & 3;
        const int gate = (lane >> 2) & 3;
        const int hl2  = 2 * warp + (lane >> 4);
        const int row  = gate * HH + 32 * (int)R + hl2;
        float wl[12], wr[24];
#pragma unroll
        for (int m = 0; m < 12; m++) {
            const int p = 12 * j + m;
            wl[m] = (p < 16) ? W_ih[(size_t)row * II + p]
                             : W_hh[(size_t)row * HH + 32 * (int)R + (p - 16)];
        }
#pragma unroll
        for (int m = 0; m < 24; m++) {
            const int q = 24 * j + m;
            int sr = q >> 5;                       // sender slot index 0..2
            const int r = (sr < (int)R) ? sr : sr + 1;  // actual sender rank
            wr[m] = W_hh[(size_t)row * HH + 32 * r + (q & 31)];
        }
#pragma unroll
        for (int m = 0; m < 6; m++)  w2l[m] = pack2(wl[2 * m], wl[2 * m + 1]);
#pragma unroll
        for (int m = 0; m < 12; m++) w2r[m] = pack2(wr[2 * m], wr[2 * m + 1]);
        if (j == 0) biasPack = pack2(b_ih[row] + b_hh[row], 0.0f);
        // owner lanes (0 and 16): send targets for this lane's own h value
        if (owner) {
            const int hoff = 2 * warp + (lane >> 4);     // h index within my 32-block
#pragma unroll
            for (int c3 = 0; c3 < 3; c3++) {
                const int c  = (int)((R + 1 + c3) & 3);
                const int ix = ((int)R < c) ? (int)R : (int)R - 1;
                peerh[c3] = pbase[c] + (uint32_t)((OFF_HX + VHR + 32 * ix + hoff) * 4);
                peerm[c3] = pbase[c] + OFF_MBAR_BYTES;
            }
        }
        // Pre-loop: local partial for step 0 over slot 0 (x(0), h_local=0)
        const ulonglong2* hlp = (const ulonglong2*)(smf + OFF_HX + 12 * j);
        u64 aA = biasPack, aB = 0;
#pragma unroll
        for (int m = 0; m < 3; m++) {
            ulonglong2 h2 = hlp[m];
            aA = ffma2(w2l[2 * m],     h2.x, aA);
            aB = ffma2(w2l[2 * m + 1], h2.y, aB);
        }
        aLA = aA; aLB = aB;
    }
    // FC warp (16)
    float wfc0 = 0.f, wfc1 = 0.f, wfc2 = 0.f, bfc0 = 0.f, bfc1 = 0.f, bfc2 = 0.f;
    if (warp == 16) {
        const int hi = 32 * (int)R + lane;
        wfc0 = W_fc[hi]; wfc1 = W_fc[HH + hi]; wfc2 = W_fc[2 * HH + hi];
        if (R == 0 && lane == 0) { bfc0 = b_fc[0]; bfc1 = b_fc[1]; bfc2 = b_fc[2]; }
    }
    // Comm warp (17): lanes 0..7 hold x(t+1) as float2
    float2 xr = make_float2(0.f, 0.f);
    if (warp == 17 && lane < 8)
        xr = ((const float2*)(x + ((size_t)b * TT + 1) * II))[lane];

    int pid = 0;
    unsigned par0 = 0, par1 = 0, par2 = 0;
    int cur = 0;

    // ---- Time loop ----
    for (int t = 0; t < TT; t++) {
        int nxt = cur + 1; if (nxt == 3) nxt = 0;
        const float* hxc = smf + OFF_HX + cur * HXF;
        const uint32_t mbo = (uint32_t)(OFF_MBAR_BYTES + 8 * nxt);

        if (tid < 512) {
            if (t > 0) {
                unsigned parity = (cur == 0) ? par0 : ((cur == 1) ? par1 : par2);
                mbar_wait(sbase + OFF_MBAR_BYTES + 8 * cur, parity);
                if (cur == 0) par0 ^= 1; else if (cur == 1) par1 ^= 1; else par2 ^= 1;
            }
            // Remote dot (96 wide) on top of saved local partial
            u64 aA = aLA, aB = aLB;
            const ulonglong2* hr = (const ulonglong2*)(hxc + VHR + 24 * j);
#pragma unroll
            for (int m = 0; m < 6; m++) {
                ulonglong2 h2 = hr[m];
                aA = ffma2(w2r[2 * m],     h2.x, aA);
                aB = ffma2(w2r[2 * m + 1], h2.y, aB);
            }
            float a0, a1, a2, a3;
            unpack2(a0, a1, aA);
            unpack2(a2, a3, aB);
            float pre = (a0 + a1) + (a2 + a3);
            pre += __shfl_xor_sync(0xffffffffu, pre, 1);
            pre += __shfl_xor_sync(0xffffffffu, pre, 2);
            const int gate = (lane >> 2) & 3;
            float act = (gate == 2) ? tanh_ap(pre) : sig_ap(pre);
            const int b16 = lane & 16;
            float vi = __shfl_sync(0xffffffffu, act, b16);
            float vf = __shfl_sync(0xffffffffu, act, b16 + 4);
            float vg = __shfl_sync(0xffffffffu, act, b16 + 8);
            float vo = __shfl_sync(0xffffffffu, act, b16 + 12);
            if (owner) {                      // lanes 0,16 own h[2*warp + (lane>>4)]
                c_state = fmaf(vf, c_state, vi * vg);
                float hval = vo * tanh_ap(c_state);
                const uint32_t slotB = (uint32_t)(nxt * HXF * 4);
#pragma unroll
                for (int c3 = 0; c3 < 3; c3++)
                    st_async_b32(peerh[c3] + slotB, hval, peerm[c3] + 8 * nxt);
                // local h_local STS (ordered by the syncthreads below)
                smf[OFF_HX + nxt * HXF + VHL + 2 * warp + (lane >> 4)] = hval;
            }
        } else if (warp == 16) {
            // FC for h(t-1): slot cur local region; pid captured last step from x(t-1)[2]
            const int pid_next = (int)hxc[VX + 2];    // x(t)[2]
            if (t > 0) {
                float hv = hxc[VHL + lane];
                float p0 = hv * wfc0, p1 = hv * wfc1, p2 = hv * wfc2;
#pragma unroll
                for (int o = 16; o > 0; o >>= 1) {
                    p0 += __shfl_down_sync(0xffffffffu, p0, o);
                    p1 += __shfl_down_sync(0xffffffffu, p1, o);
                    p2 += __shfl_down_sync(0xffffffffu, p2, o);
                }
                if (lane == 0 && (unsigned)pid < PP) {
                    float* s = &smf[OFF_SUMS + pid * 3];
                    s[0] += p0 + bfc0; s[1] += p1 + bfc1; s[2] += p2 + bfc2;
                    if (R == 0) smf[OFF_CNT + pid] += 1.0f;
                }
            }
            pid = pid_next;
        } else {
            // Comm warp: x(t+1) into slot nxt (plain STS), expect_tx(nxt), prefetch x(t+2)
            if (lane == 16) {
                mbar_expect_tx(sbase + mbo, TXB);
            } else if (lane < 8) {
                *(float2*)&smf[OFF_HX + nxt * HXF + VX + 2 * lane] = xr;
                xr = (t + 2 < TT)
                   ? ((const float2*)(x + ((size_t)b * TT + t + 2) * II))[lane]
                   : make_float2(0.f, 0.f);
            }
        }
        __syncthreads();
        // Shadow work: local partial dot for step t+1 over slot nxt [x(t+1) | h_local(t)]
        if (tid < 512) {
            const ulonglong2* hlp = (const ulonglong2*)(smf + OFF_HX + nxt * HXF + 12 * j);
            u64 aA = biasPack, aB = 0;
#pragma unroll
            for (int m = 0; m < 3; m++) {
                ulonglong2 h2 = hlp[m];
                aA = ffma2(w2l[2 * m],     h2.x, aA);
                aB = ffma2(w2l[2 * m + 1], h2.y, aB);
            }
            aLA = aA; aLB = aB;
        }
        cur = nxt;
    }

    // ---- Final FC round for h(TT-1): slot 2 local region (8191%3==1 -> nxt==2) ----
    if (warp == 16) {
        const float* hxc = smf + OFF_HX + 2 * HXF;
        float hv = hxc[VHL + lane];
        float p0 = hv * wfc0, p1 = hv * wfc1, p2 = hv * wfc2;
#pragma unroll
        for (int o = 16; o > 0; o >>= 1) {
            p0 += __shfl_down_sync(0xffffffffu, p0, o);
            p1 += __shfl_down_sync(0xffffffffu, p1, o);
            p2 += __shfl_down_sync(0xffffffffu, p2, o);
        }
        if (lane == 0 && (unsigned)pid < PP) {
            float* s = &smf[OFF_SUMS + pid * 3];
            s[0] += p0 + bfc0; s[1] += p1 + bfc1; s[2] += p2 + bfc2;
            if (R == 0) smf[OFF_CNT + pid] += 1.0f;
        }
    }
    __syncthreads();
    asm volatile("barrier.cluster.arrive.aligned;" ::: "memory");
    asm volatile("barrier.cluster.wait.aligned;" ::: "memory");

    // ---- Epilogue: rank 0 gathers peer partial sums via DSMEM, writes out ----
    if (R == 0) {
        for (int idx = tid; idx < PP * OO; idx += NTHR) {
            float s = smf[OFF_SUMS + idx];
#pragma unroll
            for (int c = 1; c < CL; c++) {
                const uint32_t ra = pbase[c] + (uint32_t)((OFF_SUMS + idx) * 4);
                float v;
                asm volatile("ld.shared::cluster.f32 %0, [%1];" : "=f"(v) : "r"(ra));
                s += v;
            }
            const int p = idx / 3;
            float cc = smf[OFF_CNT + p];
            if (cc == 0.0f) cc = 1.0f;
            out[(size_t)b * PP * OO + idx] = s / cc;
        }
    }
    asm volatile("barrier.cluster.arrive.aligned;" ::: "memory");
    asm volatile("barrier.cluster.wait.aligned;" ::: "memory");
}

extern "C" void kernel_launch(void* const* d_in, const int* in_sizes, int n_in,
                              void* d_out, int out_size) {
    const float* x    = (const float*)d_in[0];
    const float* W_ih = (const float*)d_in[1];
    const float* W_hh = (const float*)d_in[2];
    const float* b_ih = (const float*)d_in[3];
    const float* b_hh = (const float*)d_in[4];
    const float* W_fc = (const float*)d_in[5];
    const float* b_fc = (const float*)d_in[6];
    float* out = (float*)d_out;
    lstm_tanhhw_kernel<<<BB * CL, NTHR>>>(x, W_ih, W_hh, b_ih, b_hh, W_fc, b_fc, out);
}